// round 8
// baseline (speedup 1.0000x reference)
#include <cuda_runtime.h>
#include <cuda_fp16.h>
#include <math.h>
#include <cstdint>

#define BB   64
#define TT   256
#define INF  512
#define HIDF 1024
#define OUTF 256
#define NDOM 20

#define F1ROW (INF * HIDF + HIDF)
#define F2ROW (HIDF * OUTF + OUTF)
#define GRIDP 296          // persistent grid: 2 CTAs x 148 SMs

__device__ __align__(16) __half g_xh[BB * TT * INF];
__device__ __align__(16) __half g_f1h[NDOM * F1ROW];
__device__ __align__(16) __half g_f2h[NDOM * F2ROW];
__device__ __align__(16) __half g_hh[BB * TT * HIDF];
__device__ int g_dom[BB];

// ---------------------------------------------------------------------------
__device__ __forceinline__ uint32_t smem_to_u32(const void* p) {
    uint32_t a;
    asm("{ .reg .u64 t; cvta.to.shared.u64 t, %1; cvt.u32.u64 %0, t; }"
        : "=r"(a) : "l"(p));
    return a;
}
#define CP_ASYNC16(dst_u32, src_ptr) \
    asm volatile("cp.async.cg.shared.global [%0], [%1], 16;" \
                 :: "r"(dst_u32), "l"(src_ptr) : "memory")
#define CP_ASYNC_COMMIT() asm volatile("cp.async.commit_group;" ::: "memory")
#define CP_ASYNC_WAIT2()  asm volatile("cp.async.wait_group 2;" ::: "memory")

#define LDSM_X4(r0, r1, r2, r3, addr) \
    asm volatile("ldmatrix.sync.aligned.m8n8.x4.shared.b16 {%0,%1,%2,%3}, [%4];" \
                 : "=r"(r0), "=r"(r1), "=r"(r2), "=r"(r3) : "r"(addr))
#define LDSM_X4_T(r0, r1, r2, r3, addr) \
    asm volatile("ldmatrix.sync.aligned.m8n8.x4.trans.shared.b16 {%0,%1,%2,%3}, [%4];" \
                 : "=r"(r0), "=r"(r1), "=r"(r2), "=r"(r3) : "r"(addr))

__device__ __forceinline__ void mma_f16(float* c, const uint32_t* a, const uint32_t* b) {
    asm volatile(
        "mma.sync.aligned.m16n8k16.row.col.f32.f16.f16.f32 "
        "{%0,%1,%2,%3}, {%4,%5,%6,%7}, {%8,%9}, {%0,%1,%2,%3};"
        : "+f"(c[0]), "+f"(c[1]), "+f"(c[2]), "+f"(c[3])
        : "r"(a[0]), "r"(a[1]), "r"(a[2]), "r"(a[3]), "r"(b[0]), "r"(b[1]));
}

__device__ __forceinline__ float gelu_erf(float v) {
    return 0.5f * v * (1.0f + erff(v * 0.70710678118654752f));
}

__host__ __device__ constexpr int ilog2c(int v) { int l = 0; while (v >>= 1) l++; return l; }

// ---------------------------------------------------------------------------
// Prep: domain decode + fp32->fp16 converts.
// Two independent float4 loads per iteration (double MLP; round-7 ncu:
// 66% HBM at issue 14.5% = latency-limited with MLP=1 per thread).
// ---------------------------------------------------------------------------
__device__ __forceinline__ void cvt_range(const float* __restrict__ src,
                                          __half* __restrict__ dst,
                                          int n4, int gtid, int gstride) {
    int i = gtid;
    for (; i + gstride < n4; i += 2 * gstride) {
        float4 v0 = *reinterpret_cast<const float4*>(src + (size_t)i * 4);
        float4 v1 = *reinterpret_cast<const float4*>(src + (size_t)(i + gstride) * 4);
        __half2 a0 = __floats2half2_rn(v0.x, v0.y);
        __half2 a1 = __floats2half2_rn(v0.z, v0.w);
        __half2 b0 = __floats2half2_rn(v1.x, v1.y);
        __half2 b1 = __floats2half2_rn(v1.z, v1.w);
        *reinterpret_cast<uint2*>(dst + (size_t)i * 4) =
            make_uint2(*(uint32_t*)&a0, *(uint32_t*)&a1);
        *reinterpret_cast<uint2*>(dst + (size_t)(i + gstride) * 4) =
            make_uint2(*(uint32_t*)&b0, *(uint32_t*)&b1);
    }
    for (; i < n4; i += gstride) {
        float4 v = *reinterpret_cast<const float4*>(src + (size_t)i * 4);
        __half2 h0 = __floats2half2_rn(v.x, v.y);
        __half2 h1 = __floats2half2_rn(v.z, v.w);
        *reinterpret_cast<uint2*>(dst + (size_t)i * 4) =
            make_uint2(*(uint32_t*)&h0, *(uint32_t*)&h1);
    }
}

__global__ void prep_kernel(const int* __restrict__ hi,
                            const float* __restrict__ x,
                            const float* __restrict__ fc1,
                            const float* __restrict__ fc2) {
    if (blockIdx.x == 0) {
        __shared__ int s_is64;
        int t = threadIdx.x;
        if (t == 0) s_is64 = 1;
        __syncthreads();
        if (t < 64 && hi[2 * t + 1] != 0) s_is64 = 0;
        __syncthreads();
        if (t < 64) g_dom[t] = s_is64 ? hi[4 * t] : hi[2 * t];
    }
    int gtid = blockIdx.x * blockDim.x + threadIdx.x;
    int gstride = gridDim.x * blockDim.x;
    cvt_range(x,   g_xh,  (BB * TT * INF) / 4, gtid, gstride);
    cvt_range(fc1, g_f1h, (NDOM * F1ROW) / 4,  gtid, gstride);
    cvt_range(fc2, g_f2h, (NDOM * F2ROW) / 4,  gtid, gstride);
}

// ---------------------------------------------------------------------------
// Persistent batched fp16 GEMM, flattened 4-stage cp.async pipeline
// (staging runs 3 k-tiles ahead; wait_group 2).
// CTA tile 128x128x32, 8 warps (2M x 4N), m16n8k16.
// ---------------------------------------------------------------------------
#define AST 40
#define BST 136
#define AELEM (128 * AST)
#define BELEM (32 * BST)
#define NSTAGE 4
#define SMEM_BYTES ((NSTAGE * AELEM + NSTAGE * BELEM) * 2)

template <int KDIM, int NDIM, int WROW, bool GELU>
__global__ void __launch_bounds__(256, 2)
gemm_f16_persist(const __half* __restrict__ Act,   // [BB][TT][KDIM]
                 const __half* __restrict__ Wtab,  // [NDOM][WROW]
                 const float* __restrict__ Ftab,   // fp32 table (bias)
                 __half* __restrict__ Ch,          // fp16 out (or null)
                 float* __restrict__ Cf)           // fp32 out (or null)
{
    constexpr int NKT    = KDIM / 32;
    constexpr int LOGNKT = ilog2c(NKT);
    constexpr int NTN    = NDIM / 128;
    constexpr int NTM    = TT / 128;
    constexpr int NTILE  = NTN * NTM;
    constexpr int LOGNTI = ilog2c(NTILE);
    constexpr int LOGNTN = ilog2c(NTN);
    constexpr int NT     = NTILE * BB;

    extern __shared__ __half smem[];
    const uint32_t as_u32 = smem_to_u32(smem);
    const uint32_t bs_u32 = as_u32 + NSTAGE * AELEM * 2;

    const int t    = threadIdx.x;
    const int lid  = t & 31;
    const int wid  = t >> 5;
    const int wm   = wid & 1;
    const int wn   = wid >> 1;
    const int gid  = lid >> 2;
    const int tid4 = lid & 3;
    const int bid  = blockIdx.x;

    const int tcount = (bid < NT) ? ((NT - bid + GRIDP - 1) / GRIDP) : 0;
    const int S = tcount << LOGNKT;
    if (S == 0) return;

    const int s_ar = t >> 2, s_akc = t & 3;
    const int s_br = t >> 4, s_bnc = t & 15;
    const int a_row   = wm * 64 + (lid & 15);
    const int a_col   = (lid >> 4) * 8;
    const int b_krow  = lid & 15;
    const int b_ncol0 = wn * 32 + (lid >> 4) * 8;

    auto stage = [&](int s, int buf) {
        const int tl = s >> LOGNKT;
        const int kt = s & (NKT - 1);
        const int ti = bid + tl * GRIDP;
        const int b  = ti >> LOGNTI;
        const int r  = ti & (NTILE - 1);
        const int m0 = (r >> LOGNTN) * 128;
        const int n0 = (r & (NTN - 1)) * 128;
        const __half* Ag = Act + ((size_t)b * TT + m0) * KDIM + kt * 32;
        const __half* Wg = Wtab + (size_t)__ldg(&g_dom[b]) * WROW
                               + (size_t)(kt * 32) * NDIM + n0;
        const uint32_t ab = as_u32 + (uint32_t)(buf * AELEM) * 2;
        const uint32_t bb = bs_u32 + (uint32_t)(buf * BELEM) * 2;
#pragma unroll
        for (int it = 0; it < 2; it++) {
            int ar = s_ar + it * 64;
            CP_ASYNC16(ab + (uint32_t)(ar * AST + s_akc * 8) * 2,
                       Ag + (size_t)ar * KDIM + s_akc * 8);
            int br = s_br + it * 16;
            CP_ASYNC16(bb + (uint32_t)(br * BST + s_bnc * 8) * 2,
                       Wg + (size_t)br * NDIM + s_bnc * 8);
        }
        CP_ASYNC_COMMIT();
    };

    float acc[4][4][4];
#pragma unroll
    for (int i = 0; i < 4; i++)
#pragma unroll
        for (int j = 0; j < 4; j++)
#pragma unroll
            for (int q = 0; q < 4; q++) acc[i][j][q] = 0.0f;

    // prologue: stage 3 k-tiles (S >= NKT >= 16 whenever we get here)
    stage(0, 0);
    stage(1, 1);
    stage(2, 2);

    int buf = 0;
    for (int s = 0; s < S; s++) {
        CP_ASYNC_WAIT2();
        __syncthreads();

        if (s + 3 < S) {
            stage(s + 3, (buf + 3) & (NSTAGE - 1));
        } else {
            CP_ASYNC_COMMIT();
        }

        const uint32_t ab = as_u32 + (uint32_t)(buf * AELEM) * 2;
        const uint32_t bb = bs_u32 + (uint32_t)(buf * BELEM) * 2;
#pragma unroll
        for (int ks = 0; ks < 2; ks++) {
            uint32_t af[4][4];
#pragma unroll
            for (int i = 0; i < 4; i++) {
                uint32_t addr = ab + (uint32_t)((a_row + i * 16) * AST + ks * 16 + a_col) * 2;
                LDSM_X4(af[i][0], af[i][1], af[i][2], af[i][3], addr);
            }
            uint32_t bf[4][2];
#pragma unroll
            for (int jp = 0; jp < 2; jp++) {
                uint32_t addr = bb + (uint32_t)((ks * 16 + b_krow) * BST + b_ncol0 + jp * 16) * 2;
                LDSM_X4_T(bf[jp * 2][0], bf[jp * 2][1], bf[jp * 2 + 1][0], bf[jp * 2 + 1][1], addr);
            }
#pragma unroll
            for (int i = 0; i < 4; i++)
#pragma unroll
                for (int j = 0; j < 4; j++)
                    mma_f16(acc[i][j], af[i], bf[j]);
        }
        buf = (buf + 1) & (NSTAGE - 1);

        // ---- tile boundary: epilogue (overlaps in-flight next-tile loads)
        if ((s & (NKT - 1)) == NKT - 1) {
            const int ti = bid + (s >> LOGNKT) * GRIDP;
            const int b  = ti >> LOGNTI;
            const int r  = ti & (NTILE - 1);
            const int m0 = (r >> LOGNTN) * 128;
            const int n0 = (r & (NTN - 1)) * 128;
            const float* bias = Ftab + (size_t)__ldg(&g_dom[b]) * WROW
                                     + (size_t)KDIM * NDIM;
#pragma unroll
            for (int i = 0; i < 4; i++) {
#pragma unroll
                for (int j = 0; j < 4; j++) {
                    int row = m0 + wm * 64 + i * 16 + gid;
                    int col = n0 + wn * 32 + j * 8 + tid4 * 2;
                    float b0 = __ldg(bias + col), b1 = __ldg(bias + col + 1);
#pragma unroll
                    for (int h = 0; h < 2; h++) {
                        float vx = acc[i][j][h * 2 + 0] + b0;
                        float vy = acc[i][j][h * 2 + 1] + b1;
                        if (GELU) { vx = gelu_erf(vx); vy = gelu_erf(vy); }
                        size_t off = (size_t)b * TT * NDIM
                                   + (size_t)(row + h * 8) * NDIM + col;
                        if (Ch) {
                            __half2 hv = __floats2half2_rn(vx, vy);
                            *reinterpret_cast<__half2*>(Ch + off) = hv;
                        } else {
                            *reinterpret_cast<float2*>(Cf + off) = make_float2(vx, vy);
                        }
                        acc[i][j][h * 2 + 0] = 0.0f;
                        acc[i][j][h * 2 + 1] = 0.0f;
                    }
                }
            }
        }
    }
}

extern "C" void kernel_launch(void* const* d_in, const int* in_sizes, int n_in,
                              void* d_out, int out_size) {
    const float* x   = (const float*)d_in[0];
    const int*   hi  = (const int*)d_in[1];
    const float* fc1 = (const float*)d_in[2];
    const float* fc2 = (const float*)d_in[3];
    float*       out = (float*)d_out;

    __half *xh, *f1h, *f2h, *hh;
    cudaGetSymbolAddress((void**)&xh,  g_xh);
    cudaGetSymbolAddress((void**)&f1h, g_f1h);
    cudaGetSymbolAddress((void**)&f2h, g_f2h);
    cudaGetSymbolAddress((void**)&hh,  g_hh);

    cudaFuncSetAttribute(gemm_f16_persist<INF, HIDF, F1ROW, true>,
                         cudaFuncAttributeMaxDynamicSharedMemorySize, SMEM_BYTES);
    cudaFuncSetAttribute(gemm_f16_persist<HIDF, OUTF, F2ROW, false>,
                         cudaFuncAttributeMaxDynamicSharedMemorySize, SMEM_BYTES);

    prep_kernel<<<1184, 256>>>(hi, x, fc1, fc2);

    // GEMM1: h(fp16) = gelu(x @ W1 + b1)
    gemm_f16_persist<INF, HIDF, F1ROW, true>
        <<<GRIDP, 256, SMEM_BYTES>>>(xh, f1h, fc1, hh, nullptr);

    // GEMM2: out(fp32) = h @ W2 + b2
    gemm_f16_persist<HIDF, OUTF, F2ROW, false>
        <<<GRIDP, 256, SMEM_BYTES>>>(hh, f2h, fc2, nullptr, out);
}